// round 7
// baseline (speedup 1.0000x reference)
#include <cuda_runtime.h>

#define BB      4096
#define DD      8192
#define KK      5
#define GS      40
#define CKLEN   17
#define NTHR    256
#define TILE    2048                    // outputs per block
#define TILES_PER_ROW (DD / TILE)       // 4

#define CNTHR   128                     // compose block size
#define CBLK    (BB / CNTHR)            // 32 compose blocks

// Composed per-row 17-tap kernels (4096 * 17 * 4B = 278 KB, L2-resident)
__device__ float g_ck[BB * CKLEN];

// ---------------------------------------------------------------------------
// Kernel 1: compose each row's 17-tap kernel. 32 blocks x 128 threads,
// one row per thread; each block redundantly reduces max_it over g (L2 hits).
// ---------------------------------------------------------------------------
__global__ void __launch_bounds__(CNTHR)
compose_kernel(const int* __restrict__ g, const float* __restrict__ kernels)
{
    __shared__ int s_red[CNTHR / 32];
    const int t = threadIdx.x;
    const int b = blockIdx.x * CNTHR + t;

    int m = 0;
    #pragma unroll 8
    for (int i = t; i < BB; i += CNTHR) {
        int gv = g[i];
        int av = gv < 0 ? -gv : gv;
        m = max(m, av / GS);
    }
    #pragma unroll
    for (int o = 16; o > 0; o >>= 1)
        m = max(m, __shfl_xor_sync(0xffffffffu, m, o));
    if ((t & 31) == 0) s_red[t >> 5] = m;
    __syncthreads();
    int max_it = s_red[0];
    #pragma unroll
    for (int w = 1; w < CNTHR / 32; w++) max_it = max(max_it, s_red[w]);

    float idk[KK], posk[KK], negk[KK];
    #pragma unroll
    for (int j = 0; j < KK; j++) {
        idk[j]  = __ldg(kernels + 40 * KK + j);
        posk[j] = __ldg(kernels + 80 * KK + j);
        negk[j] = __ldg(kernels + 0  * KK + j);
    }

    int gv  = g[b];
    int sgn = (gv > 0) - (gv < 0);
    int av  = gv < 0 ? -gv : gv;
    int it  = av / GS;
    int rem = av - it * GS;

    int fidx = rem * sgn + 40;
    float fink[KK];
    #pragma unroll
    for (int j = 0; j < KK; j++) fink[j] = __ldg(kernels + fidx * KK + j);

    float maxk[KK];
    #pragma unroll
    for (int j = 0; j < KK; j++)
        maxk[j] = (sgn > 0) ? posk[j] : ((sgn < 0) ? negk[j] : idk[j]);

    float c[CKLEN];
    #pragma unroll
    for (int p = 0; p < CKLEN; p++) c[p] = 0.f;
    c[8] = 1.f;

    #pragma unroll
    for (int stage = 0; stage < 4; stage++) {
        float kk[KK];
        bool skip = false;
        if (stage == 3) {
            #pragma unroll
            for (int j = 0; j < KK; j++) kk[j] = fink[j];
        } else if (stage < it) {
            #pragma unroll
            for (int j = 0; j < KK; j++) kk[j] = maxk[j];
        } else if (stage < max_it) {
            #pragma unroll
            for (int j = 0; j < KK; j++) kk[j] = idk[j];
        } else {
            skip = true;
        }
        if (!skip) {
            float nc[CKLEN];
            #pragma unroll
            for (int p = 0; p < CKLEN; p++) {
                float a = 0.f;
                #pragma unroll
                for (int j = 0; j < KK; j++) {
                    int q = p - j + 2;
                    if (q >= 0 && q < CKLEN) a = fmaf(kk[j], c[q], a);
                }
                nc[p] = a;
            }
            #pragma unroll
            for (int p = 0; p < CKLEN; p++) c[p] = nc[p];
        }
    }

    #pragma unroll
    for (int p = 0; p < CKLEN; p++) g_ck[b * CKLEN + p] = c[p];
}

// ---------------------------------------------------------------------------
// Kernel 2: single-pass 17-tap circular correlation, lane-interleaved float4s.
// Circular wrap via power-of-two masking: idx = (d - 8 + 4q) & (DD-1).
// No branch, no predication — one LOP3 per load replaces the old wrap logic.
// All LDG.128 / STG.128 remain fully coalesced 512B warp accesses.
// ---------------------------------------------------------------------------
__global__ void __launch_bounds__(NTHR)
conv_main(const float* __restrict__ x, float* __restrict__ out)
{
    const int bid  = blockIdx.x;
    const int b    = bid >> 2;              // TILES_PER_ROW = 4
    const int tile = bid & 3;
    const int lane = threadIdx.x & 31;
    const int warp = threadIdx.x >> 5;

    const float* __restrict__ xr = x + (size_t)b * DD;
    float* __restrict__ orow     = out + (size_t)b * DD;

    // row kernel: uniform across the block (broadcast loads)
    float k[CKLEN];
    const float* ckp = g_ck + b * CKLEN;
    #pragma unroll
    for (int j = 0; j < CKLEN; j++) k[j] = __ldg(ckp + j);

    const int base4 = tile * (TILE / 4) + warp * 64 + lane;  // float4 index, round 0

    #pragma unroll
    for (int r = 0; r < 2; r++) {
        const int d  = (base4 + r * 32) * 4;   // first output of this float4
        const int t0 = d - 8;

        // window x[(d-8 .. d+11) mod DD]: 5 masked, coalesced LDG.128
        float w[20];
        #pragma unroll
        for (int q = 0; q < 5; q++) {
            const int idx = (t0 + 4 * q) & (DD - 1);   // circular, float4-aligned
            float4 v = __ldg(reinterpret_cast<const float4*>(xr + idx));
            w[4 * q + 0] = v.x;
            w[4 * q + 1] = v.y;
            w[4 * q + 2] = v.z;
            w[4 * q + 3] = v.w;
        }

        // out[d+i] = sum_p k[p] * w[i+p]
        float a0 = 0.f, a1 = 0.f, a2 = 0.f, a3 = 0.f;
        #pragma unroll
        for (int p = 0; p < CKLEN; p++) {
            a0 = fmaf(k[p], w[p + 0], a0);
            a1 = fmaf(k[p], w[p + 1], a1);
            a2 = fmaf(k[p], w[p + 2], a2);
            a3 = fmaf(k[p], w[p + 3], a3);
        }

        __stcs(reinterpret_cast<float4*>(orow + d), make_float4(a0, a1, a2, a3));
    }
}

// ---------------------------------------------------------------------------
// Launch
// ---------------------------------------------------------------------------
extern "C" void kernel_launch(void* const* d_in, const int* in_sizes, int n_in,
                              void* d_out, int out_size)
{
    const float* x       = (const float*)d_in[0];   // [4096, 8192] f32
    const int*   g       = (const int*)  d_in[1];   // [4096] i32
    const float* kernels = (const float*)d_in[2];   // [81, 5] f32
    float*       out     = (float*)d_out;           // [4096, 1, 8192] f32

    compose_kernel<<<CBLK, CNTHR>>>(g, kernels);
    conv_main<<<BB * TILES_PER_ROW, NTHR>>>(x, out);
}

// round 8
// speedup vs baseline: 1.0857x; 1.0857x over previous
#include <cuda_runtime.h>

#define BB      4096
#define DD      8192
#define KK      5
#define GS      40
#define CKLEN   17
#define CKPAD   20                      // padded row length (5 aligned float4s)
#define NTHR    256
#define TILE    2048                    // outputs per block
#define TILES_PER_ROW (DD / TILE)       // 4

#define CNTHR   128                     // compose block size
#define CBLK    (BB / CNTHR)            // 32 compose blocks

// Composed per-row 17-tap kernels, padded to 20 floats (327 KB, L2-resident)
__device__ float g_ck[BB * CKPAD];

// ---------------------------------------------------------------------------
// Kernel 1: compose each row's 17-tap kernel. 32 blocks x 128 threads,
// one row per thread; each block redundantly reduces max_it over g (L2 hits).
// ---------------------------------------------------------------------------
__global__ void __launch_bounds__(CNTHR)
compose_kernel(const int* __restrict__ g, const float* __restrict__ kernels)
{
    __shared__ int s_red[CNTHR / 32];
    const int t = threadIdx.x;
    const int b = blockIdx.x * CNTHR + t;

    int m = 0;
    #pragma unroll 8
    for (int i = t; i < BB; i += CNTHR) {
        int gv = g[i];
        int av = gv < 0 ? -gv : gv;
        m = max(m, av / GS);
    }
    #pragma unroll
    for (int o = 16; o > 0; o >>= 1)
        m = max(m, __shfl_xor_sync(0xffffffffu, m, o));
    if ((t & 31) == 0) s_red[t >> 5] = m;
    __syncthreads();
    int max_it = s_red[0];
    #pragma unroll
    for (int w = 1; w < CNTHR / 32; w++) max_it = max(max_it, s_red[w]);

    float idk[KK], posk[KK], negk[KK];
    #pragma unroll
    for (int j = 0; j < KK; j++) {
        idk[j]  = __ldg(kernels + 40 * KK + j);
        posk[j] = __ldg(kernels + 80 * KK + j);
        negk[j] = __ldg(kernels + 0  * KK + j);
    }

    int gv  = g[b];
    int sgn = (gv > 0) - (gv < 0);
    int av  = gv < 0 ? -gv : gv;
    int it  = av / GS;
    int rem = av - it * GS;

    int fidx = rem * sgn + 40;
    float fink[KK];
    #pragma unroll
    for (int j = 0; j < KK; j++) fink[j] = __ldg(kernels + fidx * KK + j);

    float maxk[KK];
    #pragma unroll
    for (int j = 0; j < KK; j++)
        maxk[j] = (sgn > 0) ? posk[j] : ((sgn < 0) ? negk[j] : idk[j]);

    float c[CKLEN];
    #pragma unroll
    for (int p = 0; p < CKLEN; p++) c[p] = 0.f;
    c[8] = 1.f;

    #pragma unroll
    for (int stage = 0; stage < 4; stage++) {
        float kk[KK];
        bool skip = false;
        if (stage == 3) {
            #pragma unroll
            for (int j = 0; j < KK; j++) kk[j] = fink[j];
        } else if (stage < it) {
            #pragma unroll
            for (int j = 0; j < KK; j++) kk[j] = maxk[j];
        } else if (stage < max_it) {
            #pragma unroll
            for (int j = 0; j < KK; j++) kk[j] = idk[j];
        } else {
            skip = true;
        }
        if (!skip) {
            float nc[CKLEN];
            #pragma unroll
            for (int p = 0; p < CKLEN; p++) {
                float a = 0.f;
                #pragma unroll
                for (int j = 0; j < KK; j++) {
                    int q = p - j + 2;
                    if (q >= 0 && q < CKLEN) a = fmaf(kk[j], c[q], a);
                }
                nc[p] = a;
            }
            #pragma unroll
            for (int p = 0; p < CKLEN; p++) c[p] = nc[p];
        }
    }

    // padded write: 17 taps + 3 zeros, as 5 aligned float4s
    float4* dst = reinterpret_cast<float4*>(g_ck + b * CKPAD);
    dst[0] = make_float4(c[0],  c[1],  c[2],  c[3]);
    dst[1] = make_float4(c[4],  c[5],  c[6],  c[7]);
    dst[2] = make_float4(c[8],  c[9],  c[10], c[11]);
    dst[3] = make_float4(c[12], c[13], c[14], c[15]);
    dst[4] = make_float4(c[16], 0.f,   0.f,   0.f);
}

// ---------------------------------------------------------------------------
// Kernel 2: single-pass 17-tap circular correlation, lane-interleaved float4s.
// Taps loaded as 5 LDG.128 (padded rows) instead of 17 LDG.32.
// 42-reg budget (launch_bounds minBlocks=6) so both rounds' loads can hoist.
// ---------------------------------------------------------------------------
__global__ void __launch_bounds__(NTHR, 6)
conv_main(const float* __restrict__ x, float* __restrict__ out)
{
    const int bid  = blockIdx.x;
    const int b    = bid >> 2;              // TILES_PER_ROW = 4
    const int tile = bid & 3;
    const int lane = threadIdx.x & 31;
    const int warp = threadIdx.x >> 5;

    const float* __restrict__ xr = x + (size_t)b * DD;
    float* __restrict__ orow     = out + (size_t)b * DD;

    // row taps: 5 vector loads (uniform across block, L1/L2 broadcast)
    float k[CKLEN];
    {
        const float4* ckp = reinterpret_cast<const float4*>(g_ck + b * CKPAD);
        float4 k0 = __ldg(ckp + 0);
        float4 k1 = __ldg(ckp + 1);
        float4 k2 = __ldg(ckp + 2);
        float4 k3 = __ldg(ckp + 3);
        float4 k4 = __ldg(ckp + 4);
        k[0]=k0.x; k[1]=k0.y; k[2]=k0.z; k[3]=k0.w;
        k[4]=k1.x; k[5]=k1.y; k[6]=k1.z; k[7]=k1.w;
        k[8]=k2.x; k[9]=k2.y; k[10]=k2.z; k[11]=k2.w;
        k[12]=k3.x; k[13]=k3.y; k[14]=k3.z; k[15]=k3.w;
        k[16]=k4.x;
    }

    const int base4 = tile * (TILE / 4) + warp * 64 + lane;  // float4 index, round 0

    #pragma unroll
    for (int r = 0; r < 2; r++) {
        const int d  = (base4 + r * 32) * 4;   // first output of this float4
        const int t0 = d - 8;

        // window x[(d-8 .. d+11) mod DD]: 5 masked, coalesced LDG.128
        float w[20];
        #pragma unroll
        for (int q = 0; q < 5; q++) {
            const int idx = (t0 + 4 * q) & (DD - 1);   // circular, float4-aligned
            float4 v = __ldg(reinterpret_cast<const float4*>(xr + idx));
            w[4 * q + 0] = v.x;
            w[4 * q + 1] = v.y;
            w[4 * q + 2] = v.z;
            w[4 * q + 3] = v.w;
        }

        // out[d+i] = sum_p k[p] * w[i+p]
        float a0 = 0.f, a1 = 0.f, a2 = 0.f, a3 = 0.f;
        #pragma unroll
        for (int p = 0; p < CKLEN; p++) {
            a0 = fmaf(k[p], w[p + 0], a0);
            a1 = fmaf(k[p], w[p + 1], a1);
            a2 = fmaf(k[p], w[p + 2], a2);
            a3 = fmaf(k[p], w[p + 3], a3);
        }

        __stcs(reinterpret_cast<float4*>(orow + d), make_float4(a0, a1, a2, a3));
    }
}

// ---------------------------------------------------------------------------
// Launch
// ---------------------------------------------------------------------------
extern "C" void kernel_launch(void* const* d_in, const int* in_sizes, int n_in,
                              void* d_out, int out_size)
{
    const float* x       = (const float*)d_in[0];   // [4096, 8192] f32
    const int*   g       = (const int*)  d_in[1];   // [4096] i32
    const float* kernels = (const float*)d_in[2];   // [81, 5] f32
    float*       out     = (float*)d_out;           // [4096, 1, 8192] f32

    compose_kernel<<<CBLK, CNTHR>>>(g, kernels);
    conv_main<<<BB * TILES_PER_ROW, NTHR>>>(x, out);
}

// round 9
// speedup vs baseline: 1.1379x; 1.0480x over previous
#include <cuda_runtime.h>

#define BB      4096
#define DD      8192
#define KK      5
#define GS      40
#define CKLEN   17
#define CKPAD   20                      // padded row length (5 aligned float4s)
#define NTHR    256
#define TILE    2048                    // outputs per block
#define TILES_PER_ROW (DD / TILE)       // 4

#define CNTHR   128                     // compose block size
#define CBLK    (BB / CNTHR)            // 32 compose blocks

// Composed per-row 17-tap kernels, padded to 20 floats (327 KB, L2-resident)
__device__ float g_ck[BB * CKPAD];

// ---------------------------------------------------------------------------
// Kernel 1: compose each row's 17-tap kernel. 32 blocks x 128 threads,
// one row per thread; each block redundantly reduces max_it over g (L2 hits).
// ---------------------------------------------------------------------------
__global__ void __launch_bounds__(CNTHR)
compose_kernel(const int* __restrict__ g, const float* __restrict__ kernels)
{
    __shared__ int s_red[CNTHR / 32];
    const int t = threadIdx.x;
    const int b = blockIdx.x * CNTHR + t;

    int m = 0;
    #pragma unroll 8
    for (int i = t; i < BB; i += CNTHR) {
        int gv = g[i];
        int av = gv < 0 ? -gv : gv;
        m = max(m, av / GS);
    }
    #pragma unroll
    for (int o = 16; o > 0; o >>= 1)
        m = max(m, __shfl_xor_sync(0xffffffffu, m, o));
    if ((t & 31) == 0) s_red[t >> 5] = m;
    __syncthreads();
    int max_it = s_red[0];
    #pragma unroll
    for (int w = 1; w < CNTHR / 32; w++) max_it = max(max_it, s_red[w]);

    float idk[KK], posk[KK], negk[KK];
    #pragma unroll
    for (int j = 0; j < KK; j++) {
        idk[j]  = __ldg(kernels + 40 * KK + j);
        posk[j] = __ldg(kernels + 80 * KK + j);
        negk[j] = __ldg(kernels + 0  * KK + j);
    }

    int gv  = g[b];
    int sgn = (gv > 0) - (gv < 0);
    int av  = gv < 0 ? -gv : gv;
    int it  = av / GS;
    int rem = av - it * GS;

    int fidx = rem * sgn + 40;
    float fink[KK];
    #pragma unroll
    for (int j = 0; j < KK; j++) fink[j] = __ldg(kernels + fidx * KK + j);

    float maxk[KK];
    #pragma unroll
    for (int j = 0; j < KK; j++)
        maxk[j] = (sgn > 0) ? posk[j] : ((sgn < 0) ? negk[j] : idk[j]);

    float c[CKLEN];
    #pragma unroll
    for (int p = 0; p < CKLEN; p++) c[p] = 0.f;
    c[8] = 1.f;

    #pragma unroll
    for (int stage = 0; stage < 4; stage++) {
        float kk[KK];
        bool skip = false;
        if (stage == 3) {
            #pragma unroll
            for (int j = 0; j < KK; j++) kk[j] = fink[j];
        } else if (stage < it) {
            #pragma unroll
            for (int j = 0; j < KK; j++) kk[j] = maxk[j];
        } else if (stage < max_it) {
            #pragma unroll
            for (int j = 0; j < KK; j++) kk[j] = idk[j];
        } else {
            skip = true;
        }
        if (!skip) {
            float nc[CKLEN];
            #pragma unroll
            for (int p = 0; p < CKLEN; p++) {
                float a = 0.f;
                #pragma unroll
                for (int j = 0; j < KK; j++) {
                    int q = p - j + 2;
                    if (q >= 0 && q < CKLEN) a = fmaf(kk[j], c[q], a);
                }
                nc[p] = a;
            }
            #pragma unroll
            for (int p = 0; p < CKLEN; p++) c[p] = nc[p];
        }
    }

    // padded write: 17 taps + 3 zeros, as 5 aligned float4s
    float4* dst = reinterpret_cast<float4*>(g_ck + b * CKPAD);
    dst[0] = make_float4(c[0],  c[1],  c[2],  c[3]);
    dst[1] = make_float4(c[4],  c[5],  c[6],  c[7]);
    dst[2] = make_float4(c[8],  c[9],  c[10], c[11]);
    dst[3] = make_float4(c[12], c[13], c[14], c[15]);
    dst[4] = make_float4(c[16], 0.f,   0.f,   0.f);
}

// ---------------------------------------------------------------------------
// Kernel 2: 17-tap circular correlation, lane-interleaved float4s.
// ALL 10 x-window loads issued up front (MLP=10/thread), then PDL-sync,
// then taps, then two compute+store phases. Launched with programmatic
// stream serialization so its load prologue overlaps compose_kernel.
// ---------------------------------------------------------------------------
__global__ void __launch_bounds__(NTHR)
conv_main(const float* __restrict__ x, float* __restrict__ out)
{
    const int bid  = blockIdx.x;
    const int b    = bid >> 2;              // TILES_PER_ROW = 4
    const int tile = bid & 3;
    const int lane = threadIdx.x & 31;
    const int warp = threadIdx.x >> 5;

    const float* __restrict__ xr = x + (size_t)b * DD;
    float* __restrict__ orow     = out + (size_t)b * DD;

    const int base4 = tile * (TILE / 4) + warp * 64 + lane;  // float4 index
    const int d0 = base4 * 4;          // round-0 first output
    const int d1 = d0 + 128;           // round-1 first output (32 float4s later)

    // ---- issue all 10 window loads (x has no dependency on compose) ----
    float w0[20], w1[20];
    #pragma unroll
    for (int q = 0; q < 5; q++) {
        const int idx = (d0 - 8 + 4 * q) & (DD - 1);
        float4 v = __ldg(reinterpret_cast<const float4*>(xr + idx));
        w0[4*q+0] = v.x; w0[4*q+1] = v.y; w0[4*q+2] = v.z; w0[4*q+3] = v.w;
    }
    #pragma unroll
    for (int q = 0; q < 5; q++) {
        const int idx = (d1 - 8 + 4 * q) & (DD - 1);
        float4 v = __ldg(reinterpret_cast<const float4*>(xr + idx));
        w1[4*q+0] = v.x; w1[4*q+1] = v.y; w1[4*q+2] = v.z; w1[4*q+3] = v.w;
    }

#if __CUDA_ARCH__ >= 900
    // wait for compose_kernel (g_ck producer) to complete
    cudaGridDependencySynchronize();
#endif

    // row taps: 5 vector loads (uniform across block, L2-resident)
    float k[CKLEN];
    {
        const float4* ckp = reinterpret_cast<const float4*>(g_ck + b * CKPAD);
        float4 k0 = __ldg(ckp + 0);
        float4 k1 = __ldg(ckp + 1);
        float4 k2 = __ldg(ckp + 2);
        float4 k3 = __ldg(ckp + 3);
        float4 k4 = __ldg(ckp + 4);
        k[0]=k0.x;  k[1]=k0.y;  k[2]=k0.z;  k[3]=k0.w;
        k[4]=k1.x;  k[5]=k1.y;  k[6]=k1.z;  k[7]=k1.w;
        k[8]=k2.x;  k[9]=k2.y;  k[10]=k2.z; k[11]=k2.w;
        k[12]=k3.x; k[13]=k3.y; k[14]=k3.z; k[15]=k3.w;
        k[16]=k4.x;
    }

    // ---- round 0 ----
    {
        float a0 = 0.f, a1 = 0.f, a2 = 0.f, a3 = 0.f;
        #pragma unroll
        for (int p = 0; p < CKLEN; p++) {
            a0 = fmaf(k[p], w0[p + 0], a0);
            a1 = fmaf(k[p], w0[p + 1], a1);
            a2 = fmaf(k[p], w0[p + 2], a2);
            a3 = fmaf(k[p], w0[p + 3], a3);
        }
        __stcs(reinterpret_cast<float4*>(orow + d0), make_float4(a0, a1, a2, a3));
    }

    // ---- round 1 ----
    {
        float a0 = 0.f, a1 = 0.f, a2 = 0.f, a3 = 0.f;
        #pragma unroll
        for (int p = 0; p < CKLEN; p++) {
            a0 = fmaf(k[p], w1[p + 0], a0);
            a1 = fmaf(k[p], w1[p + 1], a1);
            a2 = fmaf(k[p], w1[p + 2], a2);
            a3 = fmaf(k[p], w1[p + 3], a3);
        }
        __stcs(reinterpret_cast<float4*>(orow + d1), make_float4(a0, a1, a2, a3));
    }
}

// ---------------------------------------------------------------------------
// Launch: compose, then conv with programmatic dependent launch so conv's
// x-load prologue overlaps compose + launch latency.
// ---------------------------------------------------------------------------
extern "C" void kernel_launch(void* const* d_in, const int* in_sizes, int n_in,
                              void* d_out, int out_size)
{
    const float* x       = (const float*)d_in[0];   // [4096, 8192] f32
    const int*   g       = (const int*)  d_in[1];   // [4096] i32
    const float* kernels = (const float*)d_in[2];   // [81, 5] f32
    float*       out     = (float*)d_out;           // [4096, 1, 8192] f32

    compose_kernel<<<CBLK, CNTHR>>>(g, kernels);

    cudaLaunchConfig_t cfg = {};
    cfg.gridDim  = dim3(BB * TILES_PER_ROW, 1, 1);
    cfg.blockDim = dim3(NTHR, 1, 1);
    cfg.dynamicSmemBytes = 0;
    cfg.stream = 0;   // legacy default stream (same one the harness captures)
    cudaLaunchAttribute attrs[1];
    attrs[0].id = cudaLaunchAttributeProgrammaticStreamSerialization;
    attrs[0].val.programmaticStreamSerializationAllowed = 1;
    cfg.attrs = attrs;
    cfg.numAttrs = 1;
    cudaLaunchKernelEx(&cfg, conv_main, x, out);
}